// round 4
// baseline (speedup 1.0000x reference)
#include <cuda_runtime.h>

#define D_  48
#define H_  256
#define W_  256
#define DM_ 48
#define HM_ 128
#define WM_ 128
#define PH_ 4

#define XP_ (W_ + 1)   // 257 pair slots per row; slot s holds pixels (s-1, s)

// dup[(z*H_ + y)*XP_ + (x0+1)] = float4( img[z,y,x0,0],   img[z,y,x0,1],
//                                        img[z,y,x0+1,0], img[z,y,x0+1,1] )
// x0 ranges over [-1, W_-1]; out-of-range pixels are zero-filled (zeros padding).
__device__ float4 g_dup[(size_t)D_ * H_ * XP_];   // ~50.5 MB static scratch

// ---------------------------------------------------------------------------
// Kernel 1: build pair-dup layout; grid z-slice 1 copies out[:,0] = image
// ---------------------------------------------------------------------------
__global__ void __launch_bounds__(256)
fill_dup_kernel(const float* __restrict__ image, float* __restrict__ out)
{
    const int tid = threadIdx.x;
    const int y = blockIdx.x;
    const int z = blockIdx.y;

    if (blockIdx.z == 1) {
        const size_t off = ((size_t)z * H_ + y) * W_ * 2;
        const float2* src = reinterpret_cast<const float2*>(image + off);
        float2* dst = reinterpret_cast<float2*>(out + off);
        dst[tid] = src[tid];
        return;
    }

    const float* row = image + ((size_t)z * H_ + y) * W_ * 2;
    float4* drow = g_dup + ((size_t)z * H_ + y) * XP_;

    // slot s = x0+1 holds pixels (s-1, s); thread tid fills slot tid,
    // thread 0 also fills slot 256 (pixels 255, OOB).
    {
        const int s = tid;                 // 0..255
        const int xa = s - 1;
        float2 pa = (xa >= 0) ? *reinterpret_cast<const float2*>(row + 2 * xa)
                              : make_float2(0.f, 0.f);
        float2 pb = *reinterpret_cast<const float2*>(row + 2 * s);
        drow[s] = make_float4(pa.x, pa.y, pb.x, pb.y);
    }
    if (tid == 0) {
        float2 pa = *reinterpret_cast<const float2*>(row + 2 * (W_ - 1));
        drow[W_] = make_float4(pa.x, pa.y, 0.f, 0.f);
    }
}

// ---------------------------------------------------------------------------
// Kernel 2: mvf 2x upsample + trilinear warp; 4 gather LDG.128s per pixel
// ---------------------------------------------------------------------------
__global__ void __launch_bounds__(256)
mvf_warp_kernel(const float* __restrict__ mvf,     // (PH,3,DM,HM,WM)
                float* __restrict__ out)           // (5,D,H,W,2)
{
    const int tid = threadIdx.x;
    const int y = blockIdx.x;      // 0..255
    const int z = blockIdx.y;      // 0..47
    const int p = blockIdx.z;      // 0..3

    // ---- stage y-interpolated mvf row into smem ----
    __shared__ float sm[3][WM_];

    float cy = 0.5f * (float)y - 0.25f;
    float fy = floorf(cy);
    int   jy0 = (int)fy;
    float wy1 = cy - fy;
    float wy0 = 1.0f - wy1;
    int   jy1 = jy0 + 1;
    if (jy0 < 0)       { jy0 = 0;       wy0 = 0.0f; wy1 = 1.0f; }
    if (jy1 > HM_ - 1) { jy1 = HM_ - 1; wy1 = 0.0f; wy0 = 1.0f; }

    const int plane = HM_ * WM_;
    {
        const int r0 = jy0 * WM_;
        const int r1 = jy1 * WM_;
        #pragma unroll
        for (int i = tid; i < 3 * WM_; i += 256) {
            int ch = i >> 7;
            int xs = i & (WM_ - 1);
            const float* s = mvf + ((size_t)(p * 3 + ch) * DM_ + z) * plane + xs;
            sm[ch][xs] = wy0 * s[r0] + wy1 * s[r1];
        }
    }
    __syncthreads();

    // ---- per-pixel x-interp of mvf ----
    const int x = tid;
    float cx = 0.5f * (float)x - 0.25f;
    float fx = floorf(cx);
    int   jx0 = (int)fx;
    float wb = cx - fx;
    float wa = 1.0f - wb;
    int   jx1 = jx0 + 1;
    if (jx0 < 0)       { jx0 = 0;       wa = 0.0f; wb = 1.0f; }
    if (jx1 > WM_ - 1) { jx1 = WM_ - 1; wb = 0.0f; wa = 1.0f; }

    float m0 = wa * sm[0][jx0] + wb * sm[0][jx1];
    float m1 = wa * sm[1][jx0] + wb * sm[1][jx1];
    float m2 = wa * sm[2][jx0] + wb * sm[2][jx1];

    // absolute sample coords, scale (1,2,2) on (z,y,x)
    float zc = (float)z +        m0;
    float yc = (float)y + 2.0f * m1;
    float xc = (float)x + 2.0f * m2;

    float zf = floorf(zc), yf = floorf(yc), xf = floorf(xc);
    int z0 = (int)zf, y0 = (int)yf, x0 = (int)xf;
    float wz = zc - zf, wy = yc - yf, wx = xc - xf;
    float wzA = 1.0f - wz, wyA = 1.0f - wy, wxA = 1.0f - wx;

    float acc0 = 0.0f, acc1 = 0.0f;
    const int sx = x0 + 1;                         // dup slot index
    if ((unsigned)sx < (unsigned)XP_) {
        #pragma unroll
        for (int dz = 0; dz < 2; dz++) {
            int zi = z0 + dz;
            if ((unsigned)zi >= (unsigned)D_) continue;
            float wzc = dz ? wz : wzA;
            #pragma unroll
            for (int dy = 0; dy < 2; dy++) {
                int yi = y0 + dy;
                if ((unsigned)yi >= (unsigned)H_) continue;
                float wyc = wzc * (dy ? wy : wyA);
                float4 v = g_dup[((size_t)zi * H_ + yi) * XP_ + sx];
                // v.xy = pixel x0 (zero if OOB), v.zw = pixel x0+1 (zero if OOB)
                float w0 = wyc * wxA;
                float w1 = wyc * wx;
                acc0 = fmaf(w0, v.x, fmaf(w1, v.z, acc0));
                acc1 = fmaf(w0, v.y, fmaf(w1, v.w, acc1));
            }
        }
    }

    size_t o = ((size_t)((1 + p) * D_ + z) * (H_ * W_) + (size_t)(y * W_ + x)) * 2;
    *reinterpret_cast<float2*>(out + o) = make_float2(acc0, acc1);
}

extern "C" void kernel_launch(void* const* d_in, const int* in_sizes, int n_in,
                              void* d_out, int out_size)
{
    const float* image = (const float*)d_in[0];   // (1,1,48,256,256,2) fp32
    const float* mvf   = (const float*)d_in[1];   // (1,4,3,48,128,128) fp32
    float* out = (float*)d_out;                   // (1,5,48,256,256,2) fp32

    dim3 gfill(H_, D_, 2);    // slice 0: build dup ; slice 1: copy out[:,0]
    fill_dup_kernel<<<gfill, 256>>>(image, out);

    dim3 gwarp(H_, D_, PH_);
    mvf_warp_kernel<<<gwarp, 256>>>(mvf, out);
}